// round 17
// baseline (speedup 1.0000x reference)
#include <cuda_runtime.h>
#include <cuda_bf16.h>
#include <cstdint>

#define NN 1024
#define DD 256
#define HH 32
#define OUTS 64
#define NBINS 65
#define PITCHB 40     // bf16 pitch for fragment arrays (80B rows: bank-perfect LDSM)
#define PW 20         // pitch in uint32 words

// scratch for projections (device globals: no allocation allowed)
__device__ float g_left[NN * HH];
__device__ float g_right[NN * HH];
// precomputed split-bf16 weights, exact smem image: WhH|WhL|WoH|WoL (15360 B)
__device__ __align__(16) unsigned char g_wpack[15360];

// ---------------------------------------------------------------------------
// helpers
// ---------------------------------------------------------------------------
__device__ __forceinline__ uint32_t pack_bf16(float xlo, float xhi) {
    uint32_t r;
    asm("cvt.rn.bf16x2.f32 %0, %1, %2;" : "=r"(r) : "f"(xhi), "f"(xlo));
    return r;
}
// truncation split: hi = top-16-bits of fp32 (1 PRMT for the pair),
// lo = x - hi (exact), packed bf16x2. x = hi + lo with |err| ~ 2^-16 |x|.
__device__ __forceinline__ void split_pack(float x0, float x1,
                                           uint32_t& hi, uint32_t& lo) {
    uint32_t b0 = __float_as_uint(x0), b1 = __float_as_uint(x1);
    hi = __byte_perm(b0, b1, 0x7632);
    float h0 = __uint_as_float(b0 & 0xFFFF0000u);
    float h1 = __uint_as_float(b1 & 0xFFFF0000u);
    lo = pack_bf16(x0 - h0, x1 - h1);
}
__device__ __forceinline__ void mma16816(float* c, const uint32_t* a,
                                         uint32_t b0, uint32_t b1) {
    asm("mma.sync.aligned.m16n8k16.row.col.f32.bf16.bf16.f32 "
        "{%0,%1,%2,%3}, {%4,%5,%6,%7}, {%8,%9}, {%0,%1,%2,%3};"
        : "+f"(c[0]), "+f"(c[1]), "+f"(c[2]), "+f"(c[3])
        : "r"(a[0]), "r"(a[1]), "r"(a[2]), "r"(a[3]), "r"(b0), "r"(b1));
}
__device__ __forceinline__ void ldsm_x4(uint32_t* r, uint32_t addr) {
    asm volatile("ldmatrix.sync.aligned.m8n8.x4.shared.b16 {%0,%1,%2,%3}, [%4];"
                 : "=r"(r[0]), "=r"(r[1]), "=r"(r[2]), "=r"(r[3]) : "r"(addr));
}
// gelu = 0.5x(1+tanh(u)) = x - x * rcp(1 + exp2(2*log2e*u)) ; exact same
// ex2/rcp approx primitives as __expf/__fdividef, fewer surrounding ops.
__device__ __forceinline__ float gelu_tanh(float x) {
    float x2 = x * x;
    float v = x * fmaf(0.10294344f, x2, 2.30218423f);  // 2*log2e*(c1 + c2 x^2)
    float e;
    asm("ex2.approx.f32 %0, %1;" : "=f"(e) : "f"(v));
    float d = 1.0f + e;
    float r;
    asm("rcp.approx.f32 %0, %1;" : "=f"(r) : "f"(d));
    return fmaf(-x, r, x);
}

// ---------------------------------------------------------------------------
// Fused projection + weight-prep kernel.
// Blocks [0,128): proj — 8 local rows/block, W staged in smem, both sides.
// Blocks [128,143): split-bf16 weight packing into g_wpack.
// ---------------------------------------------------------------------------
#define PROJ_BLOCKS 128
#define PROJ_SMEM_BYTES ((DD * HH * 2 + 8 * DD) * 4)   // 64KB W + 8KB local

__global__ __launch_bounds__(256)
void proj_prep_kernel(const float* __restrict__ local,
                      const float* __restrict__ Wl,
                      const float* __restrict__ Wr,
                      const float* __restrict__ Wh,
                      const float* __restrict__ Wo) {
    const int bid = blockIdx.x;
    const int t   = threadIdx.x;

    if (bid >= PROJ_BLOCKS) {
        int gt = (bid - PROJ_BLOCKS) * 256 + t;      // 0..3839
        __nv_bfloat16* dst = (__nv_bfloat16*)g_wpack;
        if (gt < 32 * PITCHB) {
            int n = gt / PITCHB, k = gt % PITCHB;
            float w = (k < HH) ? Wh[k * HH + n] : 0.f;
            __nv_bfloat16 h = __float2bfloat16_rn(w);
            dst[gt]        = h;
            dst[1280 + gt] = __float2bfloat16_rn(w - __bfloat162float(h));
        } else if (gt < 32 * PITCHB + 64 * PITCHB) {
            int u = gt - 32 * PITCHB;
            int n = u / PITCHB, k = u % PITCHB;
            float w = (k < HH) ? Wo[k * OUTS + n] : 0.f;
            __nv_bfloat16 h = __float2bfloat16_rn(w);
            dst[2560 + u] = h;
            dst[5120 + u] = __float2bfloat16_rn(w - __bfloat162float(h));
        }
        return;
    }

    extern __shared__ float ps[];
    float* sWl  = ps;
    float* sWr  = ps + DD * HH;
    float* sLoc = ps + 2 * DD * HH;
    {
        const float4* wl4 = reinterpret_cast<const float4*>(Wl);
        const float4* wr4 = reinterpret_cast<const float4*>(Wr);
        float4* dl = reinterpret_cast<float4*>(sWl);
        float4* dr = reinterpret_cast<float4*>(sWr);
#pragma unroll
        for (int q = 0; q < 8; ++q) {
            dl[t + 256 * q] = wl4[t + 256 * q];
            dr[t + 256 * q] = wr4[t + 256 * q];
        }
        const float4* lo4 = reinterpret_cast<const float4*>(local + (size_t)bid * 8 * DD);
        float4* dloc = reinterpret_cast<float4*>(sLoc);
#pragma unroll
        for (int q = 0; q < 2; ++q)
            dloc[t + 256 * q] = lo4[t + 256 * q];
    }
    __syncthreads();

    const int r = t >> 5, h = t & 31;
    const int n = bid * 8 + r;
    const float* lrow = sLoc + r * DD;

    float accL = 0.f, accR = 0.f;
#pragma unroll 16
    for (int d = 0; d < DD; ++d) {
        float v = lrow[d];
        accL += v * sWl[d * HH + h];
        accR += v * sWr[d * HH + h];
    }
    g_left[n * HH + h]  = accL;
    g_right[n * HH + h] = accR;
}

// ---------------------------------------------------------------------------
// shared layout (byte offsets, all 16B aligned)
// ---------------------------------------------------------------------------
#define OFF_REL  0          // 65*36*4 = 9360
#define OFF_SL   9360       // 2048
#define OFF_SR   11408      // 2048
#define OFF_SC   13456      // 128
#define OFF_OF   13584      // 128
#define OFF_PM   13712      // 1024
#define OFF_PHI  14736      // 20480
#define OFF_PLO  35216      // 20480
#define OFF_WHH  55696      // 2560
#define OFF_WHL  58256      // 2560
#define OFF_WOH  60816      // 5120
#define OFF_WOL  65936      // 5120
#define SMEM_BYTES 71056

// ---------------------------------------------------------------------------
// Fused pair kernel: 16x16-pair tiles, 8 warps, split-bf16 mma + ldmatrix
// ---------------------------------------------------------------------------
__global__ __launch_bounds__(256, 2)
void pair_kernel(const int* __restrict__ resi,
                 const int* __restrict__ chain,
                 const int* __restrict__ batch,
                 const int* __restrict__ mask,
                 const float* __restrict__ W_relpos,
                 const float* __restrict__ ln_scale,
                 const float* __restrict__ ln_offset,
                 float* __restrict__ out) {
    extern __shared__ __align__(16) unsigned char smraw[];
    float*     sRel = (float*)(smraw + OFF_REL);
    float*     sL   = (float*)(smraw + OFF_SL);
    float*     sR   = (float*)(smraw + OFF_SR);
    float*     sSc  = (float*)(smraw + OFF_SC);
    float*     sOf  = (float*)(smraw + OFF_OF);
    int*       sPM  = (int*)(smraw + OFF_PM);
    uint32_t*  PHI  = (uint32_t*)(smraw + OFF_PHI);
    uint32_t*  PLO  = (uint32_t*)(smraw + OFF_PLO);

    const int t    = threadIdx.x;
    const int warp = t >> 5, lane = t & 31;
    const int g    = lane >> 2, tig = lane & 3;
    const int i0   = blockIdx.y * 16, j0 = blockIdx.x * 16;
    const int i    = i0 + (t >> 4), j = j0 + (t & 15);
    const int rbase = warp * 32;

    // ---- staging (mask-independent, before the or-barrier) ----
    for (int idx = t; idx < NBINS * HH; idx += 256)
        sRel[(idx >> 5) * 36 + (idx & 31)] = W_relpos[idx];
    for (int idx = t; idx < 16 * HH; idx += 256) {
        sL[idx] = g_left[i0 * HH + idx];
        sR[idx] = g_right[j0 * HH + idx];
    }
    if (t < HH) { sSc[t] = ln_scale[t]; sOf[t] = ln_offset[t]; }
    {
        const uint4* src = (const uint4*)g_wpack;
        uint4* dst = (uint4*)(smraw + OFF_WHH);
#pragma unroll
        for (int idx = t; idx < 960; idx += 256) dst[idx] = src[idx];
    }

    // ---- per-pair mask; or-barrier doubles as staging barrier ----
    const bool pm = (batch[i] == batch[j]) && (mask[i] != 0) && (mask[j] != 0);
    sPM[t] = pm;
    const int any = __syncthreads_or((int)pm);

    const float2 z2 = make_float2(0.f, 0.f);
    if (!any) {
#pragma unroll
        for (int mt = 0; mt < 2; ++mt) {
            const int r0 = rbase + mt * 16 + g, r1 = r0 + 8;
            float* p0 = out + ((size_t)((i0 + (r0 >> 4)) * NN + j0 + (r0 & 15))) * OUTS + 2 * tig;
            float* p1 = out + ((size_t)((i0 + (r1 >> 4)) * NN + j0 + (r1 & 15))) * OUTS + 2 * tig;
#pragma unroll
            for (int q = 0; q < 8; ++q) {
                __stcs(reinterpret_cast<float2*>(p0 + 8 * q), z2);
                __stcs(reinterpret_cast<float2*>(p1 + 8 * q), z2);
            }
        }
        return;
    }

    // ---- Phase A: pair build + layernorm -> split-bf16 rows ----
    {
        const bool same_chain = (batch[i] == batch[j]) && (chain[i] == chain[j]);
        int diff = resi[i] - resi[j];
        diff = min(max(diff, -32), 32) + 32;

        const float4* lp = reinterpret_cast<const float4*>(sL + (t >> 4) * HH);
        const float4* rp = reinterpret_cast<const float4*>(sR + (t & 15) * HH);
        const float4* ep = reinterpret_cast<const float4*>(&sRel[diff * 36]);

        float p[HH];
        float mu = 0.f;
#pragma unroll
        for (int h4 = 0; h4 < 8; ++h4) {
            float4 l = lp[h4], r = rp[h4], e = ep[h4];
            float4 v;
            v.x = l.x + r.x; v.y = l.y + r.y; v.z = l.z + r.z; v.w = l.w + r.w;
            if (same_chain) { v.x += e.x; v.y += e.y; v.z += e.z; v.w += e.w; }
            p[h4 * 4 + 0] = v.x; p[h4 * 4 + 1] = v.y;
            p[h4 * 4 + 2] = v.z; p[h4 * 4 + 3] = v.w;
            mu += v.x + v.y + v.z + v.w;
        }
        mu *= (1.f / HH);
        float var = 0.f;
#pragma unroll
        for (int h = 0; h < HH; ++h) { float d = p[h] - mu; var += d * d; }
        var *= (1.f / HH);
        const float rstd = rsqrtf(var + 1e-5f);

        uint32_t hiw[16], low[16];
#pragma unroll
        for (int k2 = 0; k2 < 16; ++k2) {
            float x0 = (p[2 * k2]     - mu) * rstd * sSc[2 * k2]     + sOf[2 * k2];
            float x1 = (p[2 * k2 + 1] - mu) * rstd * sSc[2 * k2 + 1] + sOf[2 * k2 + 1];
            split_pack(x0, x1, hiw[k2], low[k2]);
        }
        uint4* ph = reinterpret_cast<uint4*>(&PHI[t * PW]);
        uint4* pl = reinterpret_cast<uint4*>(&PLO[t * PW]);
#pragma unroll
        for (int q = 0; q < 4; ++q) {
            ph[q] = make_uint4(hiw[4 * q], hiw[4 * q + 1], hiw[4 * q + 2], hiw[4 * q + 3]);
            pl[q] = make_uint4(low[4 * q], low[4 * q + 1], low[4 * q + 2], low[4 * q + 3]);
        }
    }
    __syncthreads();

    // ---- ldmatrix base addresses (32-bit shared space) ----
    const uint32_t sbase = (uint32_t)__cvta_generic_to_shared(smraw);
    const uint32_t aBase = sbase + OFF_PHI +
        (uint32_t)(((rbase + (lane & 15)) * PW + (lane >> 4) * 4) << 2);
    const uint32_t bRow = (uint32_t)((8 * (lane >> 4) + (lane & 7)) * 80 +
                                     ((lane >> 3) & 1) * 16);
    const uint32_t b1Base = sbase + OFF_WHH + bRow;
    const uint32_t b2Base = sbase + OFF_WOH + bRow;

    // ---- GEMM1: C[256x32] = P @ Wh  (3-split mma), GELU in registers ----
    float acc1[2][4][4];
#pragma unroll
    for (int mt = 0; mt < 2; ++mt)
#pragma unroll
        for (int nt = 0; nt < 4; ++nt)
#pragma unroll
            for (int e = 0; e < 4; ++e) acc1[mt][nt][e] = 0.f;

#pragma unroll
    for (int kc = 0; kc < 2; ++kc) {
        uint32_t aH[2][4], aL[2][4];
        ldsm_x4(aH[0], aBase + kc * 32);
        ldsm_x4(aH[1], aBase + 1280 + kc * 32);
        ldsm_x4(aL[0], aBase + 20480 + kc * 32);
        ldsm_x4(aL[1], aBase + 20480 + 1280 + kc * 32);
        uint32_t bH[2][4], bL[2][4];
        ldsm_x4(bH[0], b1Base + kc * 32);            // nt 0,1 hi
        ldsm_x4(bH[1], b1Base + 1280 + kc * 32);     // nt 2,3 hi
        ldsm_x4(bL[0], b1Base + 2560 + kc * 32);     // nt 0,1 lo
        ldsm_x4(bL[1], b1Base + 3840 + kc * 32);     // nt 2,3 lo
#pragma unroll
        for (int nt = 0; nt < 4; ++nt) {
            const uint32_t bh0 = bH[nt >> 1][(nt & 1) * 2];
            const uint32_t bh1 = bH[nt >> 1][(nt & 1) * 2 + 1];
            const uint32_t bl0 = bL[nt >> 1][(nt & 1) * 2];
            const uint32_t bl1 = bL[nt >> 1][(nt & 1) * 2 + 1];
#pragma unroll
            for (int mt = 0; mt < 2; ++mt) {
                mma16816(acc1[mt][nt], aH[mt], bh0, bh1);
                mma16816(acc1[mt][nt], aH[mt], bl0, bl1);
                mma16816(acc1[mt][nt], aL[mt], bh0, bh1);
            }
        }
    }

    // GELU + re-split: C fragments become GEMM2 A fragments directly
    uint32_t hidH[2][2][4], hidL[2][2][4];   // [mt][kc][areg]
#pragma unroll
    for (int mt = 0; mt < 2; ++mt)
#pragma unroll
        for (int nt = 0; nt < 4; ++nt)
#pragma unroll
            for (int e = 0; e < 4; ++e)
                acc1[mt][nt][e] = gelu_tanh(acc1[mt][nt][e]);
#pragma unroll
    for (int mt = 0; mt < 2; ++mt)
#pragma unroll
        for (int kc = 0; kc < 2; ++kc) {
            const int n0 = 2 * kc, n1 = 2 * kc + 1;
            split_pack(acc1[mt][n0][0], acc1[mt][n0][1], hidH[mt][kc][0], hidL[mt][kc][0]);
            split_pack(acc1[mt][n0][2], acc1[mt][n0][3], hidH[mt][kc][1], hidL[mt][kc][1]);
            split_pack(acc1[mt][n1][0], acc1[mt][n1][1], hidH[mt][kc][2], hidL[mt][kc][2]);
            split_pack(acc1[mt][n1][2], acc1[mt][n1][3], hidH[mt][kc][3], hidL[mt][kc][3]);
        }

    // ---- GEMM2: out[256x64] = hid @ Wo, two n-halves of 32 cols ----
#pragma unroll
    for (int half = 0; half < 2; ++half) {
        float acc2[2][4][4];
#pragma unroll
        for (int mt = 0; mt < 2; ++mt)
#pragma unroll
            for (int q = 0; q < 4; ++q)
#pragma unroll
                for (int e = 0; e < 4; ++e) acc2[mt][q][e] = 0.f;

#pragma unroll
        for (int kc = 0; kc < 2; ++kc) {
#pragma unroll
            for (int p = 0; p < 2; ++p) {    // nt2 pair {half*4+2p, +1}
                uint32_t bh[4], bl[4];
                ldsm_x4(bh, b2Base + (half * 2 + p) * 1280 + kc * 32);
                ldsm_x4(bl, b2Base + 5120 + (half * 2 + p) * 1280 + kc * 32);
#pragma unroll
                for (int mt = 0; mt < 2; ++mt) {
                    mma16816(acc2[mt][2 * p],     hidH[mt][kc], bh[0], bh[1]);
                    mma16816(acc2[mt][2 * p],     hidH[mt][kc], bl[0], bl[1]);
                    mma16816(acc2[mt][2 * p],     hidL[mt][kc], bh[0], bh[1]);
                    mma16816(acc2[mt][2 * p + 1], hidH[mt][kc], bh[2], bh[3]);
                    mma16816(acc2[mt][2 * p + 1], hidH[mt][kc], bl[2], bl[3]);
                    mma16816(acc2[mt][2 * p + 1], hidL[mt][kc], bh[2], bh[3]);
                }
            }
        }

        // stores: row r, cols half*32 + 8q + 2tig (+1) — 8B sector-aligned
#pragma unroll
        for (int mt = 0; mt < 2; ++mt) {
            const int r0 = rbase + mt * 16 + g, r1 = r0 + 8;
            const bool m0 = sPM[r0], m1 = sPM[r1];
            float* p0 = out + ((size_t)((i0 + (r0 >> 4)) * NN + j0 + (r0 & 15))) * OUTS
                            + half * 32 + 2 * tig;
            float* p1 = out + ((size_t)((i0 + (r1 >> 4)) * NN + j0 + (r1 & 15))) * OUTS
                            + half * 32 + 2 * tig;
#pragma unroll
            for (int q = 0; q < 4; ++q) {
                float2 v0 = m0 ? make_float2(acc2[mt][q][0], acc2[mt][q][1]) : z2;
                float2 v1 = m1 ? make_float2(acc2[mt][q][2], acc2[mt][q][3]) : z2;
                __stcs(reinterpret_cast<float2*>(p0 + 8 * q), v0);
                __stcs(reinterpret_cast<float2*>(p1 + 8 * q), v1);
            }
        }
    }
}

// ---------------------------------------------------------------------------
extern "C" void kernel_launch(void* const* d_in, const int* in_sizes, int n_in,
                              void* d_out, int out_size) {
    const float* local = (const float*)d_in[0];
    const int*   resi  = (const int*)d_in[1];
    const int*   chain = (const int*)d_in[2];
    const int*   batch = (const int*)d_in[3];
    const int*   mask  = (const int*)d_in[4];
    const float* Wl    = (const float*)d_in[5];
    const float* Wr    = (const float*)d_in[6];
    const float* Wrel  = (const float*)d_in[7];
    const float* lns   = (const float*)d_in[8];
    const float* lno   = (const float*)d_in[9];
    const float* Wh    = (const float*)d_in[10];
    const float* Wo    = (const float*)d_in[11];
    float*       out   = (float*)d_out;

    static bool attr_set = false;
    if (!attr_set) {
        cudaFuncSetAttribute(pair_kernel,
                             cudaFuncAttributeMaxDynamicSharedMemorySize,
                             SMEM_BYTES);
        cudaFuncSetAttribute(proj_prep_kernel,
                             cudaFuncAttributeMaxDynamicSharedMemorySize,
                             PROJ_SMEM_BYTES);
        attr_set = true;
    }

    proj_prep_kernel<<<PROJ_BLOCKS + 15, 256, PROJ_SMEM_BYTES>>>(
        local, Wl, Wr, Wh, Wo);

    dim3 grid(NN / 16, NN / 16);
    pair_kernel<<<grid, 256, SMEM_BYTES>>>(resi, chain, batch, mask, Wrel,
                                           lns, lno, out);
}